// round 5
// baseline (speedup 1.0000x reference)
#include <cuda_runtime.h>
#include <math.h>

typedef unsigned long long u64;

#define EPSF 1e-6f
#define Bn 16
#define Cn 512
#define Nn 4096
#define Kn 64
#define NUM_STAGES 3
#define NCHUNK 8
#define PSZ (Bn * Cn * Kn)

// Scratch (no allocations allowed -> device globals)
__device__ float g_b[PSZ];                    // current bases           (2 MB)
__device__ float g_bnew[PSZ];                 // summed partials         (2 MB)
__device__ float g_att[(size_t)Bn * Nn * Kn]; // softmax attention      (16 MB)
__device__ float g_part[NCHUNK][PSZ];         // per-chunk partials     (16 MB)
__device__ float g_colsum[Bn * Kn];           // sum over N per (b,k)

// ---------------------------------------------------------------------------
// f32x2 helpers (Blackwell packed fp32 pipe)
__device__ __forceinline__ u64 dup2(float x) {
    u64 r;
    asm("mov.b64 %0, {%1, %1};" : "=l"(r) : "f"(x));
    return r;
}
__device__ __forceinline__ void fma2(u64& d, u64 a, u64 b) {
    asm("fma.rn.f32x2 %0, %1, %2, %0;" : "+l"(d) : "l"(a), "l"(b));
}
__device__ __forceinline__ float2 unpk(u64 v) {
    float2 r;
    asm("mov.b64 {%0, %1}, %2;" : "=f"(r.x), "=f"(r.y) : "l"(v));
    return r;
}

// Dup-operand layout: 8 k-groups of 9 u64 (8 used + 1 pad) per row.
// Per-lane read offset = kx*9 u64 = kx*18 floats -> all 8 lanes hit distinct
// bank pairs (18 mod 32 generates {0,18,4,22,8,26,12,30}) -> conflict-free.
#define GSTR 9
#define DROW (8 * GSTR)   // 72 u64 per row

// ---------------------------------------------------------------------------
// Normalize bases (l2 over C) and broadcast to all batches.
__global__ void k_init(const float* __restrict__ bases) {
    int k = blockIdx.x;
    int tid = threadIdx.x;
    float s = 0.f;
    for (int c = tid; c < Cn; c += 128) {
        float v = bases[c * Kn + k];
        s += v * v;
    }
    __shared__ float sh[128];
    sh[tid] = s;
    __syncthreads();
    for (int o = 64; o > 0; o >>= 1) {
        if (tid < o) sh[tid] += sh[tid + o];
        __syncthreads();
    }
    float inv = 1.f / (EPSF + sqrtf(sh[0]));
    for (int c = tid; c < Cn; c += 128) {
        float v = bases[c * Kn + k] * inv;
        for (int b = 0; b < Bn; b++)
            g_b[(b * Cn + c) * Kn + k] = v;
    }
}

// ---------------------------------------------------------------------------
__global__ void k_zero_cs() {
    int i = threadIdx.x;
    if (i < Bn * Kn) g_colsum[i] = 0.f;
}

// ---------------------------------------------------------------------------
// attention[b,n,k] = softmax_k( sum_c f[b,c,n] * g_b[b,c,k] ), plus colsum.
// grid (Nn/256, Bn), block 256. Tile 256n x 64k, micro 8n x 8k, f32x2 packed
// along n-pairs; b operand pre-duplicated in shared (padded groups).
__global__ __launch_bounds__(256, 2) void k_att(const float* __restrict__ f) {
    int b = blockIdx.y;
    int n0 = blockIdx.x * 256;
    int tid = threadIdx.x;
    int kx = tid & 7;    // k group (8 k each)
    int nx = tid >> 3;   // n group (8 n each), 0..31

    __shared__ __align__(16) float sf[8 * 256];    // [cc][n]
    __shared__ __align__(16) u64 sbd[8 * DROW];    // [cc][kgroup*9+j] dup-packed
    __shared__ float colsh[Kn];

    u64 acc[4][8];
#pragma unroll
    for (int p = 0; p < 4; p++)
#pragma unroll
        for (int j = 0; j < 8; j++) acc[p][j] = 0ULL;

    const float* fb = f + (size_t)b * Cn * Nn;
    const float* bb = g_b + (size_t)(b * Cn) * Kn;

    for (int c0 = 0; c0 < Cn; c0 += 8) {
#pragma unroll
        for (int t = 0; t < 2; t++) {
            int i = tid + t * 256;         // 0..511
            int cc = i >> 6, n4 = i & 63;
            *(float4*)(sf + cc * 256 + n4 * 4) =
                *(const float4*)(fb + (size_t)(c0 + cc) * Nn + n0 + n4 * 4);
        }
        if (tid < 128) {
            int cc = tid >> 4, k4 = tid & 15;   // k = k4*4..k4*4+3
            float4 v = *(const float4*)(bb + (c0 + cc) * Kn + k4 * 4);
            u64* d = sbd + cc * DROW + (k4 >> 1) * GSTR + (k4 & 1) * 4;
            d[0] = dup2(v.x); d[1] = dup2(v.y); d[2] = dup2(v.z); d[3] = dup2(v.w);
        }
        __syncthreads();
#pragma unroll
        for (int cc = 0; cc < 8; cc++) {
            const u64* ap = (const u64*)(sf + cc * 256 + nx * 8);
            u64 a0 = ap[0], a1 = ap[1], a2 = ap[2], a3 = ap[3];
            const u64* bp = sbd + cc * DROW + kx * GSTR;
#pragma unroll
            for (int j = 0; j < 8; j++) {
                u64 bd = bp[j];
                fma2(acc[0][j], a0, bd);
                fma2(acc[1][j], a1, bd);
                fma2(acc[2][j], a2, bd);
                fma2(acc[3][j], a3, bd);
            }
        }
        __syncthreads();
    }

    // Softmax over k (8-lane groups sharing nx; xor 1,2,4 stays in group)
    float cp[8];
#pragma unroll
    for (int j = 0; j < 8; j++) cp[j] = 0.f;
    float* attb = g_att + ((size_t)b * Nn + n0) * Kn;
#pragma unroll
    for (int np = 0; np < 4; np++) {
        float2 e[8];
#pragma unroll
        for (int j = 0; j < 8; j++) e[j] = unpk(acc[np][j]);
#pragma unroll
        for (int h = 0; h < 2; h++) {
            float rr[8];
#pragma unroll
            for (int j = 0; j < 8; j++) rr[j] = h ? e[j].y : e[j].x;
            float m = rr[0];
#pragma unroll
            for (int j = 1; j < 8; j++) m = fmaxf(m, rr[j]);
#pragma unroll
            for (int s = 1; s < 8; s <<= 1) m = fmaxf(m, __shfl_xor_sync(0xffffffffu, m, s));
            float sum = 0.f;
#pragma unroll
            for (int j = 0; j < 8; j++) { rr[j] = __expf(rr[j] - m); sum += rr[j]; }
#pragma unroll
            for (int s = 1; s < 8; s <<= 1) sum += __shfl_xor_sync(0xffffffffu, sum, s);
            float inv = 1.f / sum;
#pragma unroll
            for (int j = 0; j < 8; j++) { rr[j] *= inv; cp[j] += rr[j]; }
            int n = nx * 8 + np * 2 + h;
            float4* p = (float4*)(attb + (size_t)n * Kn + kx * 8);
            p[0] = make_float4(rr[0], rr[1], rr[2], rr[3]);
            p[1] = make_float4(rr[4], rr[5], rr[6], rr[7]);
        }
    }

    __syncthreads();
    if (tid < Kn) colsh[tid] = 0.f;
    __syncthreads();
#pragma unroll
    for (int j = 0; j < 8; j++) atomicAdd(&colsh[kx * 8 + j], cp[j]);
    __syncthreads();
    if (tid < Kn) atomicAdd(&g_colsum[b * Kn + tid], colsh[tid]);
}

// ---------------------------------------------------------------------------
// part[chunk][b,c,k] = sum_{n in chunk} f[b,c,n] * att[b,n,k]
// grid (NCHUNK, Cn/256, Bn), block 256. Tile 256c x 64k, micro 8c x 8k,
// f32x2 packed along c-pairs (f transposed in shared, stride 258).
__global__ __launch_bounds__(256, 2) void k_bnew(const float* __restrict__ f) {
    int b = blockIdx.z;
    int c0 = blockIdx.y * 256;
    int chunk = blockIdx.x;
    int tid = threadIdx.x;
    int kx = tid & 7;
    int cx = tid >> 3;   // 0..31

    __shared__ __align__(16) float sft[16 * 258];   // [nn][c] transposed, pad 258
    __shared__ __align__(16) u64 sad[16 * DROW];    // [nn][kgroup*9+j] dup-packed

    u64 acc[4][8];
#pragma unroll
    for (int p = 0; p < 4; p++)
#pragma unroll
        for (int j = 0; j < 8; j++) acc[p][j] = 0ULL;

    const float* fb = f + (size_t)b * Cn * Nn + (size_t)c0 * Nn;
    const float* ab = g_att + (size_t)b * Nn * Kn;

    for (int nb = chunk * (Nn / NCHUNK); nb < (chunk + 1) * (Nn / NCHUNK); nb += 16) {
#pragma unroll
        for (int t = 0; t < 4; t++) {
            int i = tid + t * 256;         // 0..1023
            int c = i >> 2, seg = i & 3;
            float4 v = *(const float4*)(fb + (size_t)c * Nn + nb + seg * 4);
            sft[(seg * 4 + 0) * 258 + c] = v.x;
            sft[(seg * 4 + 1) * 258 + c] = v.y;
            sft[(seg * 4 + 2) * 258 + c] = v.z;
            sft[(seg * 4 + 3) * 258 + c] = v.w;
        }
        {
            int nn = tid >> 4, k4 = tid & 15;
            float4 v = *(const float4*)(ab + (size_t)(nb + nn) * Kn + k4 * 4);
            u64* d = sad + nn * DROW + (k4 >> 1) * GSTR + (k4 & 1) * 4;
            d[0] = dup2(v.x); d[1] = dup2(v.y); d[2] = dup2(v.z); d[3] = dup2(v.w);
        }
        __syncthreads();
#pragma unroll
        for (int nn = 0; nn < 16; nn++) {
            u64 a0 = *(const u64*)(sft + nn * 258 + cx * 8 + 0);
            u64 a1 = *(const u64*)(sft + nn * 258 + cx * 8 + 2);
            u64 a2 = *(const u64*)(sft + nn * 258 + cx * 8 + 4);
            u64 a3 = *(const u64*)(sft + nn * 258 + cx * 8 + 6);
            const u64* bp = sad + nn * DROW + kx * GSTR;
#pragma unroll
            for (int j = 0; j < 8; j++) {
                u64 bd = bp[j];
                fma2(acc[0][j], a0, bd);
                fma2(acc[1][j], a1, bd);
                fma2(acc[2][j], a2, bd);
                fma2(acc[3][j], a3, bd);
            }
        }
        __syncthreads();
    }

    // write per-chunk partials (no atomics)
    float* pb = g_part[chunk] + ((size_t)(b * Cn + c0 + cx * 8)) * Kn + kx * 8;
#pragma unroll
    for (int p = 0; p < 4; p++) {
        float2 e[8];
#pragma unroll
        for (int j = 0; j < 8; j++) e[j] = unpk(acc[p][j]);
        float4* q0 = (float4*)(pb + (size_t)(2 * p) * Kn);
        q0[0] = make_float4(e[0].x, e[1].x, e[2].x, e[3].x);
        q0[1] = make_float4(e[4].x, e[5].x, e[6].x, e[7].x);
        float4* q1 = (float4*)(pb + (size_t)(2 * p + 1) * Kn);
        q1[0] = make_float4(e[0].y, e[1].y, e[2].y, e[3].y);
        q1[1] = make_float4(e[4].y, e[5].y, e[6].y, e[7].y);
    }
}

// ---------------------------------------------------------------------------
// g_bnew = sum over chunks of g_part (coalesced)
__global__ void k_sum() {
    int i = blockIdx.x * 256 + threadIdx.x;
    float s = 0.f;
#pragma unroll
    for (int ch = 0; ch < NCHUNK; ch++) s += g_part[ch][i];
    g_bnew[i] = s;
}

// ---------------------------------------------------------------------------
// Fused l1norm (via colsum) + l2norm over C:
//   b = b' / ((EPS+cs)*EPS + sqrt(sum_c b'^2))
__global__ void k_bnorm() {
    int blk = blockIdx.x;
    int b = blk >> 6;
    int k = blk & 63;
    int tid = threadIdx.x;

    const float* src = g_bnew + (b * Cn) * Kn + k;
    float v[4];
    float s = 0.f;
#pragma unroll
    for (int i = 0; i < 4; i++) {
        v[i] = src[(tid + i * 128) * Kn];
        s += v[i] * v[i];
    }
    __shared__ float sh[128];
    sh[tid] = s;
    __syncthreads();
    for (int o = 64; o > 0; o >>= 1) {
        if (tid < o) sh[tid] += sh[tid + o];
        __syncthreads();
    }
    float cs = g_colsum[b * Kn + k];
    float inv = 1.f / ((EPSF + cs) * EPSF + sqrtf(sh[0]));
    float* dst = g_b + (b * Cn) * Kn + k;
#pragma unroll
    for (int i = 0; i < 4; i++) dst[(tid + i * 128) * Kn] = v[i] * inv;
}

// ---------------------------------------------------------------------------
// recon[b,c,n] = sum_k g_b[b,c,k] * att[b,n,k]
// grid (Nn/64, Cn/64, Bn), block 128. Tile 64c x 64n, micro 8c x 4n.
// f32x2 packed along the reduction dim k (both operands k-contiguous).
__global__ __launch_bounds__(128) void k_recon(float* __restrict__ out) {
    int b = blockIdx.z;
    int c0 = blockIdx.y * 64;
    int n0 = blockIdx.x * 64;
    int tid = threadIdx.x;
    int nx = tid & 15;    // n lanes; thread owns n = nx + 16*j
    int cy = tid >> 4;    // 0..7; thread owns c = cy*8 + r

    __shared__ __align__(16) float sbm[64 * 64];   // [c][k]
    __shared__ __align__(16) float satr[64 * 68];  // [n][k] pad 68

    const float* bb = g_b + (size_t)((b * Cn) + c0) * Kn;
#pragma unroll
    for (int t = 0; t < 8; t++) {
        int i = tid + t * 128;
        int row = i >> 4, k4 = i & 15;
        *(float4*)(sbm + row * 64 + k4 * 4) = *(const float4*)(bb + row * Kn + k4 * 4);
    }
    const float* ab = g_att + ((size_t)b * Nn + n0) * Kn;
#pragma unroll
    for (int t = 0; t < 8; t++) {
        int i = tid + t * 128;
        int nn = i >> 4, k4 = i & 15;
        *(float4*)(satr + nn * 68 + k4 * 4) = *(const float4*)(ab + (size_t)nn * Kn + k4 * 4);
    }
    __syncthreads();

    u64 acc[8][4];
#pragma unroll
    for (int r = 0; r < 8; r++)
#pragma unroll
        for (int j = 0; j < 4; j++) acc[r][j] = 0ULL;

#pragma unroll
    for (int kp = 0; kp < Kn / 2; kp++) {
        u64 av[4];
#pragma unroll
        for (int j = 0; j < 4; j++)
            av[j] = *(const u64*)(satr + (nx + 16 * j) * 68 + 2 * kp);
#pragma unroll
        for (int r = 0; r < 8; r++) {
            u64 bv = *(const u64*)(sbm + (cy * 8 + r) * 64 + 2 * kp);
            fma2(acc[r][0], bv, av[0]);
            fma2(acc[r][1], bv, av[1]);
            fma2(acc[r][2], bv, av[2]);
            fma2(acc[r][3], bv, av[3]);
        }
    }

    float* ob = out + ((size_t)(b * Cn + c0 + cy * 8)) * Nn + n0 + nx;
#pragma unroll
    for (int r = 0; r < 8; r++)
#pragma unroll
        for (int j = 0; j < 4; j++) {
            float2 e = unpk(acc[r][j]);
            ob[(size_t)r * Nn + 16 * j] = e.x + e.y;
        }
}

// ---------------------------------------------------------------------------
extern "C" void kernel_launch(void* const* d_in, const int* in_sizes, int n_in,
                              void* d_out, int out_size) {
    const float* feats = (const float*)d_in[0];   // [16,512,64,64]
    const float* bases = (const float*)d_in[1];   // [1,512,64]
    float* out = (float*)d_out;
    (void)in_sizes; (void)n_in; (void)out_size;

    k_init<<<Kn, 128>>>(bases);

    for (int s = 0; s < NUM_STAGES; s++) {
        k_zero_cs<<<1, 1024>>>();
        {
            dim3 g(Nn / 256, Bn);
            k_att<<<g, 256>>>(feats);
        }
        {
            dim3 g(NCHUNK, Cn / 256, Bn);
            k_bnew<<<g, 256>>>(feats);
        }
        k_sum<<<PSZ / 256, 256>>>();
        k_bnorm<<<Bn * Kn, 128>>>();
    }
    {
        dim3 g(Nn / 64, Cn / 64, Bn);
        k_recon<<<g, 128>>>(out);
    }
}

// round 8
// speedup vs baseline: 1.4920x; 1.4920x over previous
#include <cuda_runtime.h>
#include <cuda_bf16.h>
#include <math.h>
typedef unsigned int u32;

#define EPSF 1e-6f
#define Bn 16
#define Cn 512
#define Nn 4096
#define Kn 64
#define NUM_STAGES 3
#define NCHUNK 8
#define PSZ (Bn * Cn * Kn)

// device scratch (no allocs allowed)
__device__ u32   g_fw[(size_t)Bn * Cn * Nn];   // packed feats words   128 MB
__device__ u32   g_bw[PSZ];                    // packed bases words     2 MB
__device__ u32   g_attw[(size_t)Bn * Nn * Kn]; // packed att [b][n][k]  16 MB
__device__ u32   g_attT[(size_t)Bn * Kn * Nn]; // packed att [b][k][n]  16 MB
__device__ float g_part[NCHUNK][PSZ];          // bnew partials         16 MB
__device__ float g_bnew[PSZ];
__device__ float g_colsum[Bn * Kn];

// word = (h = bf16(x)) | (l = bf16(x-h)) << 16 ; h+l == x to ~2^-18
__device__ __forceinline__ u32 pack_hl(float x) {
    __nv_bfloat16 h = __float2bfloat16(x);
    __nv_bfloat16 l = __float2bfloat16(x - __bfloat162float(h));
    return (u32)__bfloat16_as_ushort(h) | ((u32)__bfloat16_as_ushort(l) << 16);
}
__device__ __forceinline__ u32 swap16(u32 x) { return __byte_perm(x, x, 0x1032); }
__device__ __forceinline__ void mma_bf16(float* d, const u32* a, u32 b0, u32 b1) {
    asm volatile(
        "mma.sync.aligned.m16n8k16.row.col.f32.bf16.bf16.f32 "
        "{%0,%1,%2,%3},{%4,%5,%6,%7},{%8,%9},{%0,%1,%2,%3};"
        : "+f"(d[0]), "+f"(d[1]), "+f"(d[2]), "+f"(d[3])
        : "r"(a[0]), "r"(a[1]), "r"(a[2]), "r"(a[3]), "r"(b0), "r"(b1));
}

// ---------------------------------------------------------------------------
__global__ void k_pack(const float* __restrict__ f) {
    size_t i = ((size_t)blockIdx.x * 256 + threadIdx.x) * 4;
    float4 v = *(const float4*)(f + i);
    uint4 wv = make_uint4(pack_hl(v.x), pack_hl(v.y), pack_hl(v.z), pack_hl(v.w));
    *(uint4*)&g_fw[i] = wv;
}

// l2-normalize bases over C, broadcast to batches, store packed words
__global__ void k_init(const float* __restrict__ bases) {
    int k = blockIdx.x, tid = threadIdx.x;
    float s = 0.f;
    for (int c = tid; c < Cn; c += 128) {
        float v = bases[c * Kn + k];
        s += v * v;
    }
    __shared__ float sh[128];
    sh[tid] = s;
    __syncthreads();
    for (int o = 64; o > 0; o >>= 1) {
        if (tid < o) sh[tid] += sh[tid + o];
        __syncthreads();
    }
    float inv = 1.f / (EPSF + sqrtf(sh[0]));
    for (int c = tid; c < Cn; c += 128) {
        u32 wv = pack_hl(bases[c * Kn + k] * inv);
        for (int b = 0; b < Bn; b++) g_bw[(b * Cn + c) * Kn + k] = wv;
    }
}

__global__ void k_zero_cs() {
    int i = threadIdx.x;
    if (i < Bn * Kn) g_colsum[i] = 0.f;
}

// ---------------------------------------------------------------------------
// att[n,k] = softmax_k( sum_c f[c,n]*b[c,k] ); writes packed words + colsum.
// grid (Nn/128, Bn), 256 thr (8 warps); warp = 16n x 64k; reduce over c.
__global__ __launch_bounds__(256) void k_att(int storeT) {
    int b = blockIdx.y, n0 = blockIdx.x * 128;
    int tid = threadIdx.x, lane = tid & 31, w = tid >> 5;
    int q = lane & 3, g = lane >> 2;

    __shared__ u32 sA[16][136];   // [c-word][n]
    __shared__ u32 sB[16][72];    // [c-word][k]
    __shared__ float colsh[Kn];

    float acc[8][4];
#pragma unroll
    for (int j = 0; j < 8; j++)
#pragma unroll
        for (int i = 0; i < 4; i++) acc[j][i] = 0.f;

    const u32* fw = g_fw + (size_t)b * Cn * Nn;
    const u32* bw = g_bw + (size_t)b * Cn * Kn;

    for (int c0 = 0; c0 < Cn; c0 += 16) {
#pragma unroll
        for (int t = 0; t < 2; t++) {
            int idx = tid + t * 256;
            int c = idx >> 5, nq = idx & 31;
            *(uint4*)&sA[c][nq * 4] =
                *(const uint4*)&fw[(size_t)(c0 + c) * Nn + n0 + nq * 4];
        }
        {
            int c = tid >> 4, kq = tid & 15;
            *(uint4*)&sB[c][kq * 4] = *(const uint4*)&bw[(c0 + c) * Kn + kq * 4];
        }
        __syncthreads();
#pragma unroll
        for (int ch = 0; ch < 2; ch++) {
            u32 a[4];
            a[0] = sA[8 * ch + q][16 * w + g];
            a[1] = sA[8 * ch + q][16 * w + g + 8];
            a[2] = sA[8 * ch + q + 4][16 * w + g];
            a[3] = sA[8 * ch + q + 4][16 * w + g + 8];
#pragma unroll
            for (int fj = 0; fj < 8; fj++) {
                u32 b0 = sB[8 * ch + q][8 * fj + g];
                u32 b1 = sB[8 * ch + q + 4][8 * fj + g];
                mma_bf16(acc[fj], a, b0, b1);
                mma_bf16(acc[fj], a, swap16(b0), swap16(b1));
            }
        }
        __syncthreads();
    }

    if (tid < Kn) colsh[tid] = 0.f;

    // softmax: thread holds rows r=16w+g (regs 0,1) and r+8 (regs 2,3);
    // a row's 64 k live on the 4 lanes sharing g -> shfl_xor 1,2
    float m0 = -1e30f, m1 = -1e30f;
#pragma unroll
    for (int fj = 0; fj < 8; fj++) {
        m0 = fmaxf(m0, fmaxf(acc[fj][0], acc[fj][1]));
        m1 = fmaxf(m1, fmaxf(acc[fj][2], acc[fj][3]));
    }
    m0 = fmaxf(m0, __shfl_xor_sync(0xffffffffu, m0, 1));
    m0 = fmaxf(m0, __shfl_xor_sync(0xffffffffu, m0, 2));
    m1 = fmaxf(m1, __shfl_xor_sync(0xffffffffu, m1, 1));
    m1 = fmaxf(m1, __shfl_xor_sync(0xffffffffu, m1, 2));
    float s0 = 0.f, s1 = 0.f;
#pragma unroll
    for (int fj = 0; fj < 8; fj++) {
        acc[fj][0] = __expf(acc[fj][0] - m0);
        acc[fj][1] = __expf(acc[fj][1] - m0);
        acc[fj][2] = __expf(acc[fj][2] - m1);
        acc[fj][3] = __expf(acc[fj][3] - m1);
        s0 += acc[fj][0] + acc[fj][1];
        s1 += acc[fj][2] + acc[fj][3];
    }
    s0 += __shfl_xor_sync(0xffffffffu, s0, 1);
    s0 += __shfl_xor_sync(0xffffffffu, s0, 2);
    s1 += __shfl_xor_sync(0xffffffffu, s1, 1);
    s1 += __shfl_xor_sync(0xffffffffu, s1, 2);
    float i0 = 1.f / s0, i1 = 1.f / s1;

    __syncthreads();  // colsh zeroed

    u32* attb = g_attw + (size_t)b * Nn * Kn;
    u32* aTb = g_attT + (size_t)b * Kn * Nn;
    int r = n0 + 16 * w + g;
#pragma unroll
    for (int fj = 0; fj < 8; fj++) {
        float v0 = acc[fj][0] * i0, v1 = acc[fj][1] * i0;
        float v2 = acc[fj][2] * i1, v3 = acc[fj][3] * i1;
        int k0 = 8 * fj + 2 * q;
        *(uint2*)&attb[(size_t)r * Kn + k0] = make_uint2(pack_hl(v0), pack_hl(v1));
        *(uint2*)&attb[(size_t)(r + 8) * Kn + k0] = make_uint2(pack_hl(v2), pack_hl(v3));
        if (storeT) {
            aTb[(size_t)k0 * Nn + r] = pack_hl(v0);
            aTb[(size_t)(k0 + 1) * Nn + r] = pack_hl(v1);
            aTb[(size_t)k0 * Nn + r + 8] = pack_hl(v2);
            aTb[(size_t)(k0 + 1) * Nn + r + 8] = pack_hl(v3);
        }
        float cs0 = v0 + v2, cs1 = v1 + v3;   // this thread's 2 rows
#pragma unroll
        for (int s = 4; s < 32; s <<= 1) {    // reduce over g
            cs0 += __shfl_xor_sync(0xffffffffu, cs0, s);
            cs1 += __shfl_xor_sync(0xffffffffu, cs1, s);
        }
        if (lane < 4) {
            atomicAdd(&colsh[k0], cs0);
            atomicAdd(&colsh[k0 + 1], cs1);
        }
    }
    __syncthreads();
    if (tid < Kn) atomicAdd(&g_colsum[b * Kn + tid], colsh[tid]);
}

// ---------------------------------------------------------------------------
// part[c,k] = sum_{n in chunk} f[c,n]*att[n,k]
// grid (Cn/128, NCHUNK, Bn), 256 thr; warp = 16c x 64k; reduce over n.
__global__ __launch_bounds__(256) void k_bnew() {
    int b = blockIdx.z, chunk = blockIdx.y, ct = blockIdx.x * 128;
    int tid = threadIdx.x, lane = tid & 31, w = tid >> 5;
    int q = lane & 3, g = lane >> 2;

    __shared__ u32 sA[128][20];   // [c][n-word]
    __shared__ u32 sB[16][72];    // [n-word][k]

    float acc[8][4];
#pragma unroll
    for (int j = 0; j < 8; j++)
#pragma unroll
        for (int i = 0; i < 4; i++) acc[j][i] = 0.f;

    const u32* fw = g_fw + (size_t)b * Cn * Nn + (size_t)ct * Nn;
    const u32* aw = g_attw + (size_t)b * Nn * Kn;

    for (int nb = chunk * (Nn / NCHUNK); nb < (chunk + 1) * (Nn / NCHUNK); nb += 16) {
#pragma unroll
        for (int t = 0; t < 2; t++) {
            int idx = tid + t * 256;
            int c = idx >> 2, nq = idx & 3;
            *(uint4*)&sA[c][nq * 4] = *(const uint4*)&fw[(size_t)c * Nn + nb + nq * 4];
        }
        {
            int nn = tid >> 4, kq = tid & 15;
            *(uint4*)&sB[nn][kq * 4] =
                *(const uint4*)&aw[(size_t)(nb + nn) * Kn + kq * 4];
        }
        __syncthreads();
#pragma unroll
        for (int ch = 0; ch < 2; ch++) {
            u32 a[4];
            a[0] = sA[16 * w + g][8 * ch + q];
            a[1] = sA[16 * w + g + 8][8 * ch + q];
            a[2] = sA[16 * w + g][8 * ch + q + 4];
            a[3] = sA[16 * w + g + 8][8 * ch + q + 4];
#pragma unroll
            for (int fj = 0; fj < 8; fj++) {
                u32 b0 = sB[8 * ch + q][8 * fj + g];
                u32 b1 = sB[8 * ch + q + 4][8 * fj + g];
                mma_bf16(acc[fj], a, b0, b1);
                mma_bf16(acc[fj], a, swap16(b0), swap16(b1));
            }
        }
        __syncthreads();
    }

    float* pb = g_part[chunk] + (size_t)(b * Cn + ct) * Kn;
    int c = 16 * w + g;
#pragma unroll
    for (int fj = 0; fj < 8; fj++) {
        int k0 = 8 * fj + 2 * q;
        *(float2*)&pb[(size_t)c * Kn + k0] = make_float2(acc[fj][0], acc[fj][1]);
        *(float2*)&pb[(size_t)(c + 8) * Kn + k0] = make_float2(acc[fj][2], acc[fj][3]);
    }
}

// ---------------------------------------------------------------------------
__global__ void k_sum() {
    int i = blockIdx.x * 256 + threadIdx.x;
    float s = 0.f;
#pragma unroll
    for (int ch = 0; ch < NCHUNK; ch++) s += g_part[ch][i];
    g_bnew[i] = s;
}

// fused l1(via colsum)+l2 norm; writes packed base words
__global__ void k_bnorm() {
    int blk = blockIdx.x, b = blk >> 6, k = blk & 63, tid = threadIdx.x;
    const float* src = g_bnew + (b * Cn) * Kn + k;
    float v[4], s = 0.f;
#pragma unroll
    for (int i = 0; i < 4; i++) {
        v[i] = src[(tid + i * 128) * Kn];
        s += v[i] * v[i];
    }
    __shared__ float sh[128];
    sh[tid] = s;
    __syncthreads();
    for (int o = 64; o > 0; o >>= 1) {
        if (tid < o) sh[tid] += sh[tid + o];
        __syncthreads();
    }
    float cs = g_colsum[b * Kn + k];
    float inv = 1.f / ((EPSF + cs) * EPSF + sqrtf(sh[0]));
    u32* dst = g_bw + (b * Cn) * Kn + k;
#pragma unroll
    for (int i = 0; i < 4; i++) dst[(tid + i * 128) * Kn] = pack_hl(v[i] * inv);
}

// ---------------------------------------------------------------------------
// out[c,n] = sum_k b[c,k]*att[n,k];  A = b words [c][k-word] (SMEM),
// B = attT words (direct LDG, L1/L2 reuse). grid (Nn/64, Cn/128, Bn), 256 thr.
__global__ __launch_bounds__(256) void k_recon(float* __restrict__ out) {
    int b = blockIdx.z, ct = blockIdx.y * 128, n0 = blockIdx.x * 64;
    int tid = threadIdx.x, lane = tid & 31, w = tid >> 5;
    int q = lane & 3, g = lane >> 2;

    __shared__ u32 sA[128][68];   // [c][k-word]

    const u32* bw = g_bw + (size_t)(b * Cn + ct) * Kn;
#pragma unroll
    for (int t = 0; t < 8; t++) {
        int idx = tid + t * 256;
        int c = idx >> 4, kq = idx & 15;
        *(uint4*)&sA[c][kq * 4] = *(const uint4*)&bw[(size_t)c * Kn + kq * 4];
    }
    __syncthreads();

    const u32* at = g_attT + (size_t)b * Kn * Nn + n0;
    float acc[8][4];
#pragma unroll
    for (int j = 0; j < 8; j++)
#pragma unroll
        for (int i = 0; i < 4; i++) acc[j][i] = 0.f;

#pragma unroll
    for (int ch = 0; ch < 8; ch++) {
        u32 a[4];
        a[0] = sA[16 * w + g][8 * ch + q];
        a[1] = sA[16 * w + g + 8][8 * ch + q];
        a[2] = sA[16 * w + g][8 * ch + q + 4];
        a[3] = sA[16 * w + g + 8][8 * ch + q + 4];
#pragma unroll
        for (int fj = 0; fj < 8; fj++) {
            u32 b0 = __ldg(&at[(size_t)(8 * ch + q) * Nn + 8 * fj + g]);
            u32 b1 = __ldg(&at[(size_t)(8 * ch + q + 4) * Nn + 8 * fj + g]);
            mma_bf16(acc[fj], a, b0, b1);
            mma_bf16(acc[fj], a, swap16(b0), swap16(b1));
        }
    }

    float* ob = out + (size_t)(b * Cn + ct) * Nn + n0;
    int c = 16 * w + g;
#pragma unroll
    for (int fj = 0; fj < 8; fj++) {
        int n = 8 * fj + 2 * q;
        *(float2*)&ob[(size_t)c * Nn + n] = make_float2(acc[fj][0], acc[fj][1]);
        *(float2*)&ob[(size_t)(c + 8) * Nn + n] = make_float2(acc[fj][2], acc[fj][3]);
    }
}

// ---------------------------------------------------------------------------
extern "C" void kernel_launch(void* const* d_in, const int* in_sizes, int n_in,
                              void* d_out, int out_size) {
    const float* feats = (const float*)d_in[0];
    const float* bases = (const float*)d_in[1];
    float* out = (float*)d_out;
    (void)in_sizes; (void)n_in; (void)out_size;

    k_pack<<<(int)(((size_t)Bn * Cn * Nn / 4) / 256), 256>>>(feats);
    k_init<<<Kn, 128>>>(bases);

    for (int s = 0; s < NUM_STAGES; s++) {
        k_zero_cs<<<1, 1024>>>();
        k_att<<<dim3(Nn / 128, Bn), 256>>>(s == NUM_STAGES - 1 ? 1 : 0);
        k_bnew<<<dim3(Cn / 128, NCHUNK, Bn), 256>>>();
        k_sum<<<PSZ / 256, 256>>>();
        k_bnorm<<<Bn * Kn, 128>>>();
    }
    k_recon<<<dim3(Nn / 64, Cn / 128, Bn), 256>>>(out);
}

// round 9
// speedup vs baseline: 1.6940x; 1.1354x over previous
#include <cuda_runtime.h>
#include <cuda_bf16.h>
#include <math.h>
typedef unsigned int u32;

#define EPSF 1e-6f
#define Bn 16
#define Cn 512
#define Nn 4096
#define Kn 64
#define NUM_STAGES 3
#define NCHUNK 8
#define PSZ (Bn * Cn * Kn)

// device scratch (no allocs allowed)
__device__ u32   g_fw[(size_t)Bn * Cn * Nn];   // packed feats words   128 MB
__device__ u32   g_bw[PSZ];                    // packed bases words     2 MB
__device__ u32   g_attw[(size_t)Bn * Nn * Kn]; // packed att [b][n][k]  16 MB
__device__ u32   g_attT[(size_t)Bn * Kn * Nn]; // packed att [b][k][n]  16 MB
__device__ float g_part[NCHUNK][PSZ];          // bnew partials         16 MB
__device__ float g_bnew[PSZ];
__device__ float g_colsum[Bn * Kn];

// word = (h = bf16(x)) | (l = bf16(x-h)) << 16 ; h+l == x to ~2^-18
__device__ __forceinline__ u32 pack_hl(float x) {
    __nv_bfloat16 h = __float2bfloat16(x);
    __nv_bfloat16 l = __float2bfloat16(x - __bfloat162float(h));
    return (u32)__bfloat16_as_ushort(h) | ((u32)__bfloat16_as_ushort(l) << 16);
}
__device__ __forceinline__ u32 swap16(u32 x) { return __byte_perm(x, x, 0x1032); }
__device__ __forceinline__ void mma_bf16(float* d, const u32* a, u32 b0, u32 b1) {
    asm volatile(
        "mma.sync.aligned.m16n8k16.row.col.f32.bf16.bf16.f32 "
        "{%0,%1,%2,%3},{%4,%5,%6,%7},{%8,%9},{%0,%1,%2,%3};"
        : "+f"(d[0]), "+f"(d[1]), "+f"(d[2]), "+f"(d[3])
        : "r"(a[0]), "r"(a[1]), "r"(a[2]), "r"(a[3]), "r"(b0), "r"(b1));
}

// ---------------------------------------------------------------------------
__global__ void k_pack(const float* __restrict__ f) {
    size_t i = ((size_t)blockIdx.x * 256 + threadIdx.x) * 4;
    float4 v = *(const float4*)(f + i);
    uint4 wv = make_uint4(pack_hl(v.x), pack_hl(v.y), pack_hl(v.z), pack_hl(v.w));
    *(uint4*)&g_fw[i] = wv;
}

// l2-normalize bases over C, broadcast to batches, store packed words
__global__ void k_init(const float* __restrict__ bases) {
    int k = blockIdx.x, tid = threadIdx.x;
    float s = 0.f;
    for (int c = tid; c < Cn; c += 128) {
        float v = bases[c * Kn + k];
        s += v * v;
    }
    __shared__ float sh[128];
    sh[tid] = s;
    __syncthreads();
    for (int o = 64; o > 0; o >>= 1) {
        if (tid < o) sh[tid] += sh[tid + o];
        __syncthreads();
    }
    float inv = 1.f / (EPSF + sqrtf(sh[0]));
    for (int c = tid; c < Cn; c += 128) {
        u32 wv = pack_hl(bases[c * Kn + k] * inv);
        for (int b = 0; b < Bn; b++) g_bw[(b * Cn + c) * Kn + k] = wv;
    }
}

__global__ void k_zero_cs() {
    int i = threadIdx.x;
    if (i < Bn * Kn) g_colsum[i] = 0.f;
}

// ---------------------------------------------------------------------------
// att[n,k] = softmax_k( sum_c f[c,n]*b[c,k] ); packed words out + colsum.
// grid (Nn/256, Bn), 256 thr (8 warps); warp = 32n x 64k (2 m-subtiles).
__global__ __launch_bounds__(256, 2) void k_att(int storeT) {
    int b = blockIdx.y, n0 = blockIdx.x * 256;
    int tid = threadIdx.x, lane = tid & 31, w = tid >> 5;
    int q = lane & 3, g = lane >> 2;

    __shared__ u32 sA[16][264];   // [c-word][n], pad 8 (264%32==8 -> cf reads)
    __shared__ u32 sB[16][72];    // [c-word][k]
    __shared__ float colsh[Kn];

    float acc[2][8][4];
#pragma unroll
    for (int mt = 0; mt < 2; mt++)
#pragma unroll
        for (int j = 0; j < 8; j++)
#pragma unroll
            for (int i = 0; i < 4; i++) acc[mt][j][i] = 0.f;

    const u32* fw = g_fw + (size_t)b * Cn * Nn;
    const u32* bw = g_bw + (size_t)b * Cn * Kn;

    for (int c0 = 0; c0 < Cn; c0 += 16) {
#pragma unroll
        for (int t = 0; t < 4; t++) {      // stage A: 16 c-words x 256 n
            int idx = tid + t * 256;
            int c = idx >> 6, nq = idx & 63;
            *(uint4*)&sA[c][nq * 4] =
                *(const uint4*)&fw[(size_t)(c0 + c) * Nn + n0 + nq * 4];
        }
        {                                   // stage B: 16 c-words x 64 k
            int c = tid >> 4, kq = tid & 15;
            *(uint4*)&sB[c][kq * 4] = *(const uint4*)&bw[(c0 + c) * Kn + kq * 4];
        }
        __syncthreads();
#pragma unroll
        for (int ch = 0; ch < 2; ch++) {
            u32 a[2][4];
#pragma unroll
            for (int mt = 0; mt < 2; mt++) {
                int m = 32 * w + 16 * mt + g;
                a[mt][0] = sA[8 * ch + q][m];
                a[mt][1] = sA[8 * ch + q][m + 8];
                a[mt][2] = sA[8 * ch + q + 4][m];
                a[mt][3] = sA[8 * ch + q + 4][m + 8];
            }
#pragma unroll
            for (int fj = 0; fj < 8; fj++) {
                u32 b0 = sB[8 * ch + q][8 * fj + g];
                u32 b1 = sB[8 * ch + q + 4][8 * fj + g];
                u32 b0s = swap16(b0), b1s = swap16(b1);
                mma_bf16(acc[0][fj], a[0], b0, b1);
                mma_bf16(acc[0][fj], a[0], b0s, b1s);
                mma_bf16(acc[1][fj], a[1], b0, b1);
                mma_bf16(acc[1][fj], a[1], b0s, b1s);
            }
        }
        __syncthreads();
    }

    if (tid < Kn) colsh[tid] = 0.f;

    u32* attb = g_attw + (size_t)b * Nn * Kn;
    u32* aTb = g_attT + (size_t)b * Kn * Nn;
    float cacc0[8], cacc1[8];
#pragma unroll
    for (int fj = 0; fj < 8; fj++) { cacc0[fj] = 0.f; cacc1[fj] = 0.f; }

#pragma unroll
    for (int mt = 0; mt < 2; mt++) {
        // softmax: rows m (regs 0,1) and m+8 (regs 2,3); k spread over q lanes
        float m0 = -1e30f, m1 = -1e30f;
#pragma unroll
        for (int fj = 0; fj < 8; fj++) {
            m0 = fmaxf(m0, fmaxf(acc[mt][fj][0], acc[mt][fj][1]));
            m1 = fmaxf(m1, fmaxf(acc[mt][fj][2], acc[mt][fj][3]));
        }
        m0 = fmaxf(m0, __shfl_xor_sync(0xffffffffu, m0, 1));
        m0 = fmaxf(m0, __shfl_xor_sync(0xffffffffu, m0, 2));
        m1 = fmaxf(m1, __shfl_xor_sync(0xffffffffu, m1, 1));
        m1 = fmaxf(m1, __shfl_xor_sync(0xffffffffu, m1, 2));
        float s0 = 0.f, s1 = 0.f;
#pragma unroll
        for (int fj = 0; fj < 8; fj++) {
            acc[mt][fj][0] = __expf(acc[mt][fj][0] - m0);
            acc[mt][fj][1] = __expf(acc[mt][fj][1] - m0);
            acc[mt][fj][2] = __expf(acc[mt][fj][2] - m1);
            acc[mt][fj][3] = __expf(acc[mt][fj][3] - m1);
            s0 += acc[mt][fj][0] + acc[mt][fj][1];
            s1 += acc[mt][fj][2] + acc[mt][fj][3];
        }
        s0 += __shfl_xor_sync(0xffffffffu, s0, 1);
        s0 += __shfl_xor_sync(0xffffffffu, s0, 2);
        s1 += __shfl_xor_sync(0xffffffffu, s1, 1);
        s1 += __shfl_xor_sync(0xffffffffu, s1, 2);
        float i0 = 1.f / s0, i1 = 1.f / s1;

        int r = n0 + 32 * w + 16 * mt + g;
#pragma unroll
        for (int fj = 0; fj < 8; fj++) {
            float v0 = acc[mt][fj][0] * i0, v1 = acc[mt][fj][1] * i0;
            float v2 = acc[mt][fj][2] * i1, v3 = acc[mt][fj][3] * i1;
            int k0 = 8 * fj + 2 * q;
            *(uint2*)&attb[(size_t)r * Kn + k0] = make_uint2(pack_hl(v0), pack_hl(v1));
            *(uint2*)&attb[(size_t)(r + 8) * Kn + k0] = make_uint2(pack_hl(v2), pack_hl(v3));
            if (storeT) {
                aTb[(size_t)k0 * Nn + r] = pack_hl(v0);
                aTb[(size_t)(k0 + 1) * Nn + r] = pack_hl(v1);
                aTb[(size_t)k0 * Nn + r + 8] = pack_hl(v2);
                aTb[(size_t)(k0 + 1) * Nn + r + 8] = pack_hl(v3);
            }
            cacc0[fj] += v0 + v2;
            cacc1[fj] += v1 + v3;
        }
    }
    __syncthreads();   // colsh zeroed
#pragma unroll
    for (int fj = 0; fj < 8; fj++) {
#pragma unroll
        for (int s = 4; s < 32; s <<= 1) {  // reduce over g lanes
            cacc0[fj] += __shfl_xor_sync(0xffffffffu, cacc0[fj], s);
            cacc1[fj] += __shfl_xor_sync(0xffffffffu, cacc1[fj], s);
        }
        if (lane < 4) {
            atomicAdd(&colsh[8 * fj + 2 * q], cacc0[fj]);
            atomicAdd(&colsh[8 * fj + 2 * q + 1], cacc1[fj]);
        }
    }
    __syncthreads();
    if (tid < Kn) atomicAdd(&g_colsum[b * Kn + tid], colsh[tid]);
}

// ---------------------------------------------------------------------------
// part[c,k] = sum_{n in chunk} f[c,n]*att[n,k]
// grid (Cn/256, NCHUNK, Bn), 256 thr; warp = 32c x 64k (2 m-subtiles).
__global__ __launch_bounds__(256, 2) void k_bnew() {
    int b = blockIdx.z, chunk = blockIdx.y, ct = blockIdx.x * 256;
    int tid = threadIdx.x, lane = tid & 31, w = tid >> 5;
    int q = lane & 3, g = lane >> 2;

    __shared__ u32 sA[256][20];   // [c][n-word], pad 4
    __shared__ u32 sB[16][72];    // [n-word][k]

    float acc[2][8][4];
#pragma unroll
    for (int mt = 0; mt < 2; mt++)
#pragma unroll
        for (int j = 0; j < 8; j++)
#pragma unroll
            for (int i = 0; i < 4; i++) acc[mt][j][i] = 0.f;

    const u32* fw = g_fw + (size_t)b * Cn * Nn + (size_t)ct * Nn;
    const u32* aw = g_attw + (size_t)b * Nn * Kn;

    for (int nb = chunk * (Nn / NCHUNK); nb < (chunk + 1) * (Nn / NCHUNK); nb += 16) {
#pragma unroll
        for (int t = 0; t < 4; t++) {      // stage A: 256 c x 16 n-words
            int idx = tid + t * 256;
            int c = idx >> 2, nq = idx & 3;
            *(uint4*)&sA[c][nq * 4] = *(const uint4*)&fw[(size_t)c * Nn + nb + nq * 4];
        }
        {                                   // stage B: 16 n-words x 64 k
            int nn = tid >> 4, kq = tid & 15;
            *(uint4*)&sB[nn][kq * 4] =
                *(const uint4*)&aw[(size_t)(nb + nn) * Kn + kq * 4];
        }
        __syncthreads();
#pragma unroll
        for (int ch = 0; ch < 2; ch++) {
            u32 a[2][4];
#pragma unroll
            for (int mt = 0; mt < 2; mt++) {
                int m = 32 * w + 16 * mt + g;
                a[mt][0] = sA[m][8 * ch + q];
                a[mt][1] = sA[m + 8][8 * ch + q];
                a[mt][2] = sA[m][8 * ch + q + 4];
                a[mt][3] = sA[m + 8][8 * ch + q + 4];
            }
#pragma unroll
            for (int fj = 0; fj < 8; fj++) {
                u32 b0 = sB[8 * ch + q][8 * fj + g];
                u32 b1 = sB[8 * ch + q + 4][8 * fj + g];
                u32 b0s = swap16(b0), b1s = swap16(b1);
                mma_bf16(acc[0][fj], a[0], b0, b1);
                mma_bf16(acc[0][fj], a[0], b0s, b1s);
                mma_bf16(acc[1][fj], a[1], b0, b1);
                mma_bf16(acc[1][fj], a[1], b0s, b1s);
            }
        }
        __syncthreads();
    }

    float* pb = g_part[chunk] + (size_t)(b * Cn + ct) * Kn;
#pragma unroll
    for (int mt = 0; mt < 2; mt++) {
        int c = 32 * w + 16 * mt + g;
#pragma unroll
        for (int fj = 0; fj < 8; fj++) {
            int k0 = 8 * fj + 2 * q;
            *(float2*)&pb[(size_t)c * Kn + k0] =
                make_float2(acc[mt][fj][0], acc[mt][fj][1]);
            *(float2*)&pb[(size_t)(c + 8) * Kn + k0] =
                make_float2(acc[mt][fj][2], acc[mt][fj][3]);
        }
    }
}

// ---------------------------------------------------------------------------
__global__ void k_sum() {
    int i = blockIdx.x * 256 + threadIdx.x;
    float s = 0.f;
#pragma unroll
    for (int ch = 0; ch < NCHUNK; ch++) s += g_part[ch][i];
    g_bnew[i] = s;
}

// fused l1(via colsum)+l2 norm; writes packed base words; zeroes colsum
__global__ void k_bnorm() {
    int blk = blockIdx.x, b = blk >> 6, k = blk & 63, tid = threadIdx.x;
    const float* src = g_bnew + (b * Cn) * Kn + k;
    float v[4], s = 0.f;
#pragma unroll
    for (int i = 0; i < 4; i++) {
        v[i] = src[(tid + i * 128) * Kn];
        s += v[i] * v[i];
    }
    __shared__ float sh[128];
    sh[tid] = s;
    __syncthreads();
    for (int o = 64; o > 0; o >>= 1) {
        if (tid < o) sh[tid] += sh[tid + o];
        __syncthreads();
    }
    float cs = g_colsum[b * Kn + k];
    float inv = 1.f / ((EPSF + cs) * EPSF + sqrtf(sh[0]));
    u32* dst = g_bw + (b * Cn) * Kn + k;
#pragma unroll
    for (int i = 0; i < 4; i++) dst[(tid + i * 128) * Kn] = pack_hl(v[i] * inv);
    __syncthreads();
    if (tid == 0) g_colsum[b * Kn + k] = 0.f;   // ready for next stage
}

// ---------------------------------------------------------------------------
// out[c,n] = sum_k b[c,k]*att[n,k]; A = b words [c][k-word] (SMEM),
// B = attT words staged through SMEM in two 32-kword halves.
// grid (Nn/64, Cn/128, Bn), 256 thr; warp = 16c x 64n.
__global__ __launch_bounds__(256) void k_recon(float* __restrict__ out) {
    int b = blockIdx.z, ct = blockIdx.y * 128, n0 = blockIdx.x * 64;
    int tid = threadIdx.x, lane = tid & 31, w = tid >> 5;
    int q = lane & 3, g = lane >> 2;

    __shared__ u32 sA[128][68];   // [c][k-word]  34 KB
    __shared__ u32 sB[32][72];    // [k-word][n]   9 KB

    const u32* bw = g_bw + (size_t)(b * Cn + ct) * Kn;
#pragma unroll
    for (int t = 0; t < 8; t++) {
        int idx = tid + t * 256;
        int c = idx >> 4, kq = idx & 15;
        *(uint4*)&sA[c][kq * 4] = *(const uint4*)&bw[(size_t)c * Kn + kq * 4];
    }

    const u32* at = g_attT + (size_t)b * Kn * Nn + n0;
    float acc[8][4];
#pragma unroll
    for (int j = 0; j < 8; j++)
#pragma unroll
        for (int i = 0; i < 4; i++) acc[j][i] = 0.f;

#pragma unroll
    for (int half = 0; half < 2; half++) {
        __syncthreads();
#pragma unroll
        for (int t = 0; t < 2; t++) {      // stage B: 32 k-words x 64 n
            int idx = tid + t * 256;
            int kw = idx >> 4, nq = idx & 15;
            *(uint4*)&sB[kw][nq * 4] =
                *(const uint4*)&at[(size_t)(32 * half + kw) * Nn + nq * 4];
        }
        __syncthreads();
#pragma unroll
        for (int chl = 0; chl < 4; chl++) {
            int colb = 32 * half + 8 * chl;
            u32 a[4];
            a[0] = sA[16 * w + g][colb + q];
            a[1] = sA[16 * w + g + 8][colb + q];
            a[2] = sA[16 * w + g][colb + q + 4];
            a[3] = sA[16 * w + g + 8][colb + q + 4];
#pragma unroll
            for (int fj = 0; fj < 8; fj++) {
                u32 b0 = sB[8 * chl + q][8 * fj + g];
                u32 b1 = sB[8 * chl + q + 4][8 * fj + g];
                mma_bf16(acc[fj], a, b0, b1);
                mma_bf16(acc[fj], a, swap16(b0), swap16(b1));
            }
        }
    }

    float* ob = out + (size_t)(b * Cn + ct) * Nn + n0;
    int c = 16 * w + g;
#pragma unroll
    for (int fj = 0; fj < 8; fj++) {
        int n = 8 * fj + 2 * q;
        *(float2*)&ob[(size_t)c * Nn + n] = make_float2(acc[fj][0], acc[fj][1]);
        *(float2*)&ob[(size_t)(c + 8) * Nn + n] = make_float2(acc[fj][2], acc[fj][3]);
    }
}

// ---------------------------------------------------------------------------
extern "C" void kernel_launch(void* const* d_in, const int* in_sizes, int n_in,
                              void* d_out, int out_size) {
    const float* feats = (const float*)d_in[0];
    const float* bases = (const float*)d_in[1];
    float* out = (float*)d_out;
    (void)in_sizes; (void)n_in; (void)out_size;

    k_pack<<<(int)(((size_t)Bn * Cn * Nn / 4) / 256), 256>>>(feats);
    k_init<<<Kn, 128>>>(bases);
    k_zero_cs<<<1, 1024>>>();

    for (int s = 0; s < NUM_STAGES; s++) {
        k_att<<<dim3(Nn / 256, Bn), 256>>>(s == NUM_STAGES - 1 ? 1 : 0);
        k_bnew<<<dim3(Cn / 256, NCHUNK, Bn), 256>>>();
        k_sum<<<PSZ / 256, 256>>>();
        k_bnorm<<<Bn * Kn, 128>>>();
    }
    k_recon<<<dim3(Nn / 64, Cn / 128, Bn), 256>>>(out);
}